// round 3
// baseline (speedup 1.0000x reference)
#include <cuda_runtime.h>

#define Hh 256
#define Tt 187
#define Bb 1024
#define Cc 5
#define MB 4
#define NCTA (Bb / MB)   // 256 CTAs -> 2 per SM

// Packed weight scratch: layout [k/4][j][4] so thread j loads a float4 of
// 4 consecutive k's for its column j, coalesced across lanes (16B/lane).
__device__ float g_Wp0[Hh * Hh];      // packed W_hh0
__device__ float g_Wpih1[Hh * Hh];    // packed W_ih1
__device__ float g_Wp1[Hh * Hh];      // packed W_hh1

__global__ void pack_kernel(const float* __restrict__ W_hh0,
                            const float* __restrict__ W_ih1,
                            const float* __restrict__ W_hh1) {
    int j = blockIdx.x;      // output column (row of W)
    int k = threadIdx.x;     // input index
    int src = j * Hh + k;                       // coalesced read across k
    int dst = ((k >> 2) * Hh + j) * 4 + (k & 3);
    g_Wp0[dst]   = W_hh0[src];
    g_Wpih1[dst] = W_ih1[src];
    g_Wp1[dst]   = W_hh1[src];
}

union F2U { unsigned long long u; float2 f; };

__device__ __forceinline__ unsigned long long f32x2_fma(
    unsigned long long a, unsigned long long b, unsigned long long c) {
    unsigned long long d;
    asm("fma.rn.f32x2 %0, %1, %2, %3;" : "=l"(d) : "l"(a), "l"(b), "l"(c));
    return d;
}

__global__ void __launch_bounds__(256, 2) rnn_fused_kernel(
    const float* __restrict__ x,
    const float* __restrict__ W_ih0,
    const float* __restrict__ b_ih0, const float* __restrict__ b_hh0,
    const float* __restrict__ b_ih1, const float* __restrict__ b_hh1,
    const float* __restrict__ W_fc,  const float* __restrict__ b_fc,
    float* __restrict__ out)
{
    // Double-buffered hidden states: [buf][b][H]
    __shared__ __align__(16) float h0s[2][MB * Hh];
    __shared__ __align__(16) float h1s[2][MB * Hh];
    __shared__ float xs[MB * Tt];

    const int j  = threadIdx.x;        // this thread owns hidden column j
    const int b0 = blockIdx.x * MB;    // first batch row of this CTA

    // x rows b0..b0+MB-1 are contiguous in memory: coalesced bulk copy.
    for (int i = j; i < MB * Tt; i += 256) xs[i] = x[b0 * Tt + i];
    for (int i = j; i < MB * Hh; i += 256) {
        h0s[0][i] = 0.f; h0s[1][i] = 0.f;
        h1s[0][i] = 0.f; h1s[1][i] = 0.f;
    }

    const float wih0  = W_ih0[j];
    const float bias0 = b_ih0[j] + b_hh0[j];
    const float bias1 = b_ih1[j] + b_hh1[j];

    __syncthreads();

    int cur = 0;
    for (int t = 0; t < Tt; ++t) {
        const int nxt = cur ^ 1;
        // ---------------- layer 0: h0' = tanh(x*Wih0 + bias + h0 @ Whh0^T) ---
        unsigned long long acc[MB];
        #pragma unroll
        for (int b = 0; b < MB; ++b) acc[b] = 0ULL;

        #pragma unroll 8
        for (int k4 = 0; k4 < Hh / 4; ++k4) {
            const ulonglong2 w =
                *reinterpret_cast<const ulonglong2*>(&g_Wp0[(k4 * Hh + j) * 4]);
            #pragma unroll
            for (int b = 0; b < MB; ++b) {
                ulonglong2 h =
                    *reinterpret_cast<const ulonglong2*>(&h0s[cur][b * Hh + k4 * 4]);
                acc[b] = f32x2_fma(h.x, w.x, acc[b]);
                acc[b] = f32x2_fma(h.y, w.y, acc[b]);
            }
        }

        #pragma unroll
        for (int b = 0; b < MB; ++b) {
            F2U u; u.u = acc[b];
            float pre = xs[b * Tt + t] * wih0 + bias0 + (u.f.x + u.f.y);
            h0s[nxt][b * Hh + j] = tanhf(pre);   // nxt not read by anyone yet
        }
        __syncthreads();                          // h0' visible to all

        // ------- layer 1: h1' = tanh(h0' @ Wih1^T + bias + h1 @ Whh1^T) ------
        #pragma unroll
        for (int b = 0; b < MB; ++b) acc[b] = 0ULL;

        #pragma unroll 8
        for (int k4 = 0; k4 < Hh / 4; ++k4) {
            const ulonglong2 wa =
                *reinterpret_cast<const ulonglong2*>(&g_Wpih1[(k4 * Hh + j) * 4]);
            const ulonglong2 wb =
                *reinterpret_cast<const ulonglong2*>(&g_Wp1[(k4 * Hh + j) * 4]);
            #pragma unroll
            for (int b = 0; b < MB; ++b) {
                ulonglong2 ha =
                    *reinterpret_cast<const ulonglong2*>(&h0s[nxt][b * Hh + k4 * 4]);
                ulonglong2 hb =
                    *reinterpret_cast<const ulonglong2*>(&h1s[cur][b * Hh + k4 * 4]);
                acc[b] = f32x2_fma(ha.x, wa.x, acc[b]);
                acc[b] = f32x2_fma(ha.y, wa.y, acc[b]);
                acc[b] = f32x2_fma(hb.x, wb.x, acc[b]);
                acc[b] = f32x2_fma(hb.y, wb.y, acc[b]);
            }
        }
        #pragma unroll
        for (int b = 0; b < MB; ++b) {
            F2U u; u.u = acc[b];
            h1s[nxt][b * Hh + j] = tanhf(bias1 + (u.f.x + u.f.y));
        }
        __syncthreads();                          // h1' visible; old bufs free
        cur = nxt;
    }

    // ---------------- final FC: out[b] = h1_last @ W_fc^T + b_fc -------------
    if (j < Cc * MB) {
        int c = j / MB, b = j % MB;
        float s = b_fc[c];
        #pragma unroll 8
        for (int h = 0; h < Hh; ++h) s += h1s[cur][b * Hh + h] * W_fc[c * Hh + h];
        out[(b0 + b) * Cc + c] = s;
    }
}

extern "C" void kernel_launch(void* const* d_in, const int* in_sizes, int n_in,
                              void* d_out, int out_size) {
    const float* x     = (const float*)d_in[0];
    const float* W_ih0 = (const float*)d_in[1];
    const float* W_hh0 = (const float*)d_in[2];
    const float* b_ih0 = (const float*)d_in[3];
    const float* b_hh0 = (const float*)d_in[4];
    const float* W_ih1 = (const float*)d_in[5];
    const float* W_hh1 = (const float*)d_in[6];
    const float* b_ih1 = (const float*)d_in[7];
    const float* b_hh1 = (const float*)d_in[8];
    const float* W_fc  = (const float*)d_in[9];
    const float* b_fc  = (const float*)d_in[10];
    float* out = (float*)d_out;

    pack_kernel<<<Hh, Hh>>>(W_hh0, W_ih1, W_hh1);
    rnn_fused_kernel<<<NCTA, 256>>>(x, W_ih0, b_ih0, b_hh0,
                                    b_ih1, b_hh1, W_fc, b_fc, out);
}

// round 5
// speedup vs baseline: 1.1546x; 1.1546x over previous
#include <cuda_runtime.h>

#define Hh 256
#define Tt 187
#define Bb 1024
#define Cc 5
#define MB 8
#define NCTA (Bb / MB)   // 128 CTAs
#define Jt 4             // columns per thread
#define JTH 64           // j-threads (64 * Jt = 256 columns)
#define THR 128          // JTH * 2 k-groups

// Packed weights: layout [k/4][j][4] so a thread loads float4 of 4 consecutive
// k's for column j, coalesced across lanes (16B/lane, lanes = consecutive j).
__device__ float g_Wp0[Hh * Hh];      // packed W_hh0
__device__ float g_Wpih1[Hh * Hh];    // packed W_ih1
__device__ float g_Wp1[Hh * Hh];      // packed W_hh1

__global__ void pack_kernel(const float* __restrict__ W_hh0,
                            const float* __restrict__ W_ih1,
                            const float* __restrict__ W_hh1) {
    int j = blockIdx.x;
    int k = threadIdx.x;
    int src = j * Hh + k;
    int dst = ((k >> 2) * Hh + j) * 4 + (k & 3);
    g_Wp0[dst]   = W_hh0[src];
    g_Wpih1[dst] = W_ih1[src];
    g_Wp1[dst]   = W_hh1[src];
}

union F2U { unsigned long long u; float2 f; };

__device__ __forceinline__ unsigned long long f32x2_fma(
    unsigned long long a, unsigned long long b, unsigned long long c) {
    unsigned long long d;
    asm("fma.rn.f32x2 %0, %1, %2, %3;" : "=l"(d) : "l"(a), "l"(b), "l"(c));
    return d;
}
__device__ __forceinline__ unsigned long long f32x2_add(
    unsigned long long a, unsigned long long b) {
    unsigned long long d;
    asm("add.rn.f32x2 %0, %1, %2;" : "=l"(d) : "l"(a), "l"(b));
    return d;
}

__global__ void __launch_bounds__(THR, 1) rnn_fused_kernel(
    const float* __restrict__ x,
    const float* __restrict__ W_ih0,
    const float* __restrict__ b_ih0, const float* __restrict__ b_hh0,
    const float* __restrict__ b_ih1, const float* __restrict__ b_hh1,
    const float* __restrict__ W_fc,  const float* __restrict__ b_fc,
    float* __restrict__ out)
{
    __shared__ __align__(16) float h0s[MB * Hh];
    __shared__ __align__(16) float h1s[MB * Hh];
    // kg=1 partial sums: [c*8+b][jj] — lanes (consecutive jj) conflict-free
    __shared__ __align__(16) unsigned long long part[Jt * MB * JTH];  // 16 KB
    __shared__ float xs[MB * Tt];

    const int t  = threadIdx.x;
    const int jj = t & (JTH - 1);      // base column
    const int kg = t >> 6;             // k-group: warps 0,1 = 0; warps 2,3 = 1
    const int b0 = blockIdx.x * MB;

    for (int i = t; i < MB * Tt; i += THR) xs[i] = x[b0 * Tt + i];
    for (int i = t; i < MB * Hh; i += THR) { h0s[i] = 0.f; h1s[i] = 0.f; }

    float wih0[Jt], bias0[Jt], bias1[Jt];
    #pragma unroll
    for (int c = 0; c < Jt; ++c) {
        int j = jj + 64 * c;
        wih0[c]  = W_ih0[j];
        bias0[c] = b_ih0[j] + b_hh0[j];
        bias1[c] = b_ih1[j] + b_hh1[j];
    }

    __syncthreads();

    const int k4lo = kg * 32;

    for (int step = 0; step < Tt; ++step) {
        // ======== layer 0: h0' = tanh(x*Wih0 + bias0 + h0 @ Whh0^T) ==========
        unsigned long long acc[Jt][MB];
        #pragma unroll
        for (int c = 0; c < Jt; ++c)
            #pragma unroll
            for (int b = 0; b < MB; ++b) acc[c][b] = 0ULL;

        #pragma unroll 4
        for (int kk = 0; kk < 32; ++kk) {
            const int k4 = k4lo + kk;
            ulonglong2 w[Jt];
            #pragma unroll
            for (int c = 0; c < Jt; ++c)
                w[c] = *reinterpret_cast<const ulonglong2*>(
                    &g_Wp0[(k4 * Hh + jj + 64 * c) * 4]);
            #pragma unroll
            for (int b = 0; b < MB; ++b) {
                ulonglong2 h =
                    *reinterpret_cast<const ulonglong2*>(&h0s[b * Hh + k4 * 4]);
                #pragma unroll
                for (int c = 0; c < Jt; ++c) {
                    acc[c][b] = f32x2_fma(h.x, w[c].x, acc[c][b]);
                    acc[c][b] = f32x2_fma(h.y, w[c].y, acc[c][b]);
                }
            }
        }

        if (kg) {
            #pragma unroll
            for (int c = 0; c < Jt; ++c)
                #pragma unroll
                for (int b = 0; b < MB; ++b)
                    part[(c * MB + b) * JTH + jj] = acc[c][b];
        }
        __syncthreads();
        if (!kg) {
            #pragma unroll
            for (int c = 0; c < Jt; ++c)
                #pragma unroll
                for (int b = 0; b < MB; ++b) {
                    F2U u;
                    u.u = f32x2_add(acc[c][b], part[(c * MB + b) * JTH + jj]);
                    float pre = xs[b * Tt + step] * wih0[c] + bias0[c]
                              + (u.f.x + u.f.y);
                    h0s[b * Hh + jj + 64 * c] = tanhf(pre);
                }
        }
        __syncthreads();

        // ==== layer 1: h1' = tanh(h0' @ Wih1^T + bias1 + h1 @ Whh1^T) ========
        #pragma unroll
        for (int c = 0; c < Jt; ++c)
            #pragma unroll
            for (int b = 0; b < MB; ++b) acc[c][b] = 0ULL;

        #pragma unroll 2
        for (int kk = 0; kk < 32; ++kk) {
            const int k4 = k4lo + kk;
            ulonglong2 wa[Jt], wb[Jt];
            #pragma unroll
            for (int c = 0; c < Jt; ++c) {
                wa[c] = *reinterpret_cast<const ulonglong2*>(
                    &g_Wpih1[(k4 * Hh + jj + 64 * c) * 4]);
                wb[c] = *reinterpret_cast<const ulonglong2*>(
                    &g_Wp1[(k4 * Hh + jj + 64 * c) * 4]);
            }
            #pragma unroll
            for (int b = 0; b < MB; ++b) {
                ulonglong2 ha =
                    *reinterpret_cast<const ulonglong2*>(&h0s[b * Hh + k4 * 4]);
                ulonglong2 hb =
                    *reinterpret_cast<const ulonglong2*>(&h1s[b * Hh + k4 * 4]);
                #pragma unroll
                for (int c = 0; c < Jt; ++c) {
                    acc[c][b] = f32x2_fma(ha.x, wa[c].x, acc[c][b]);
                    acc[c][b] = f32x2_fma(ha.y, wa[c].y, acc[c][b]);
                    acc[c][b] = f32x2_fma(hb.x, wb[c].x, acc[c][b]);
                    acc[c][b] = f32x2_fma(hb.y, wb[c].y, acc[c][b]);
                }
            }
        }

        if (kg) {
            #pragma unroll
            for (int c = 0; c < Jt; ++c)
                #pragma unroll
                for (int b = 0; b < MB; ++b)
                    part[(c * MB + b) * JTH + jj] = acc[c][b];
        }
        __syncthreads();
        if (!kg) {
            #pragma unroll
            for (int c = 0; c < Jt; ++c)
                #pragma unroll
                for (int b = 0; b < MB; ++b) {
                    F2U u;
                    u.u = f32x2_add(acc[c][b], part[(c * MB + b) * JTH + jj]);
                    h1s[b * Hh + jj + 64 * c] = tanhf(bias1[c] + (u.f.x + u.f.y));
                }
        }
        __syncthreads();
    }

    // ---------------- final FC: out[b] = h1_last @ W_fc^T + b_fc -------------
    if (t < Cc * MB) {
        int c = t / MB, b = t % MB;
        float s = b_fc[c];
        #pragma unroll 8
        for (int h = 0; h < Hh; ++h) s += h1s[b * Hh + h] * W_fc[c * Hh + h];
        out[(b0 + b) * Cc + c] = s;
    }
}

extern "C" void kernel_launch(void* const* d_in, const int* in_sizes, int n_in,
                              void* d_out, int out_size) {
    const float* x     = (const float*)d_in[0];
    const float* W_ih0 = (const float*)d_in[1];
    const float* W_hh0 = (const float*)d_in[2];
    const float* b_ih0 = (const float*)d_in[3];
    const float* b_hh0 = (const float*)d_in[4];
    const float* W_ih1 = (const float*)d_in[5];
    const float* W_hh1 = (const float*)d_in[6];
    const float* b_ih1 = (const float*)d_in[7];
    const float* b_hh1 = (const float*)d_in[8];
    const float* W_fc  = (const float*)d_in[9];
    const float* b_fc  = (const float*)d_in[10];
    float* out = (float*)d_out;

    pack_kernel<<<Hh, Hh>>>(W_hh0, W_ih1, W_hh1);
    rnn_fused_kernel<<<NCTA, THR>>>(x, W_ih0, b_ih0, b_hh0,
                                    b_ih1, b_hh1, W_fc, b_fc, out);
}

// round 6
// speedup vs baseline: 1.6056x; 1.3907x over previous
#include <cuda_runtime.h>

#define Hh 256
#define Tt 187
#define Bb 1024
#define Cc 5
#define MB 8
#define NCTA (Bb / MB)   // 128 CTAs
#define THR 256          // 8 warps = 4 k-groups x 2 jj-halves

// Packed weights: layout [k/4][j][4] so a thread loads float4 of 4 consecutive
// k's for column j, coalesced across lanes (16B/lane, lanes = consecutive j).
__device__ float g_Wp0[Hh * Hh];      // packed W_hh0
__device__ float g_Wpih1[Hh * Hh];    // packed W_ih1
__device__ float g_Wp1[Hh * Hh];      // packed W_hh1

__global__ void pack_kernel(const float* __restrict__ W_hh0,
                            const float* __restrict__ W_ih1,
                            const float* __restrict__ W_hh1) {
    int j = blockIdx.x;
    int k = threadIdx.x;
    int src = j * Hh + k;
    int dst = ((k >> 2) * Hh + j) * 4 + (k & 3);
    g_Wp0[dst]   = W_hh0[src];
    g_Wpih1[dst] = W_ih1[src];
    g_Wp1[dst]   = W_hh1[src];
}

union F2U { unsigned long long u; float2 f; };

__device__ __forceinline__ unsigned long long f32x2_fma(
    unsigned long long a, unsigned long long b, unsigned long long c) {
    unsigned long long d;
    asm("fma.rn.f32x2 %0, %1, %2, %3;" : "=l"(d) : "l"(a), "l"(b), "l"(c));
    return d;
}

struct Smem {
    float h0[MB * Hh];              // 8 KB
    float h1[MB * Hh];              // 8 KB
    float part[4][4][MB][64];       // [kg][c][b][jj] 32 KB
    float xs[MB * Tt];              // ~5.9 KB
    float wih0s[Hh];
    float bias0s[Hh];
    float bias1s[Hh];
};

__global__ void __launch_bounds__(THR, 1) rnn_fused_kernel(
    const float* __restrict__ x,
    const float* __restrict__ W_ih0,
    const float* __restrict__ b_ih0, const float* __restrict__ b_hh0,
    const float* __restrict__ b_ih1, const float* __restrict__ b_hh1,
    const float* __restrict__ W_fc,  const float* __restrict__ b_fc,
    float* __restrict__ out)
{
    extern __shared__ __align__(16) char smem_raw[];
    Smem& S = *reinterpret_cast<Smem*>(smem_raw);

    const int t    = threadIdx.x;
    const int lane = t & 31;
    const int w    = t >> 5;
    const int kg   = w >> 1;           // k-group 0..3, 16 k4-iters each
    const int half = w & 1;            // jj-half
    const int jj   = half * 32 + lane; // 0..63
    const int b0   = blockIdx.x * MB;

    for (int i = t; i < MB * Tt; i += THR) S.xs[i] = x[b0 * Tt + i];
    for (int i = t; i < MB * Hh; i += THR) { S.h0[i] = 0.f; S.h1[i] = 0.f; }
    for (int i = t; i < Hh; i += THR) {
        S.wih0s[i]  = W_ih0[i];
        S.bias0s[i] = b_ih0[i] + b_hh0[i];
        S.bias1s[i] = b_ih1[i] + b_hh1[i];
    }
    __syncthreads();

    // This thread's reducer role: column colr = jj + 64*kg (warp w == task w)
    const int   colr   = jj + 64 * kg;
    const float wih0r  = S.wih0s[colr];
    const float bias0r = S.bias0s[colr];
    const float bias1r = S.bias1s[colr];

    const int k4lo = kg * 16;

    for (int step = 0; step < Tt; ++step) {
        // ========= layer 0 partials: acc[c][b] over k-slice kg ===============
        unsigned long long acc[4][MB];
        #pragma unroll
        for (int c = 0; c < 4; ++c)
            #pragma unroll
            for (int b = 0; b < MB; ++b) acc[c][b] = 0ULL;

        #pragma unroll 4
        for (int kk = 0; kk < 16; ++kk) {
            const int k4 = k4lo + kk;
            ulonglong2 wv[4];
            #pragma unroll
            for (int c = 0; c < 4; ++c)
                wv[c] = *reinterpret_cast<const ulonglong2*>(
                    &g_Wp0[(k4 * Hh + jj + 64 * c) * 4]);
            #pragma unroll
            for (int b = 0; b < MB; ++b) {
                ulonglong2 h =
                    *reinterpret_cast<const ulonglong2*>(&S.h0[b * Hh + k4 * 4]);
                #pragma unroll
                for (int c = 0; c < 4; ++c) {
                    acc[c][b] = f32x2_fma(h.x, wv[c].x, acc[c][b]);
                    acc[c][b] = f32x2_fma(h.y, wv[c].y, acc[c][b]);
                }
            }
        }
        #pragma unroll
        for (int c = 0; c < 4; ++c)
            #pragma unroll
            for (int b = 0; b < MB; ++b) {
                F2U u; u.u = acc[c][b];
                S.part[kg][c][b][jj] = u.f.x + u.f.y;
            }
        __syncthreads();

        // ========= layer 0 reduce + tanh (balanced: all 8 warps) =============
        #pragma unroll
        for (int b = 0; b < MB; ++b) {
            float s = (S.part[0][kg][b][jj] + S.part[1][kg][b][jj])
                    + (S.part[2][kg][b][jj] + S.part[3][kg][b][jj]);
            float pre = S.xs[b * Tt + step] * wih0r + bias0r + s;
            S.h0[b * Hh + colr] = tanhf(pre);
        }
        __syncthreads();

        // ========= layer 1 partials ==========================================
        #pragma unroll
        for (int c = 0; c < 4; ++c)
            #pragma unroll
            for (int b = 0; b < MB; ++b) acc[c][b] = 0ULL;

        #pragma unroll 2
        for (int kk = 0; kk < 16; ++kk) {
            const int k4 = k4lo + kk;
            ulonglong2 wa[4], wb[4];
            #pragma unroll
            for (int c = 0; c < 4; ++c) {
                wa[c] = *reinterpret_cast<const ulonglong2*>(
                    &g_Wpih1[(k4 * Hh + jj + 64 * c) * 4]);
                wb[c] = *reinterpret_cast<const ulonglong2*>(
                    &g_Wp1[(k4 * Hh + jj + 64 * c) * 4]);
            }
            #pragma unroll
            for (int b = 0; b < MB; ++b) {
                ulonglong2 ha =
                    *reinterpret_cast<const ulonglong2*>(&S.h0[b * Hh + k4 * 4]);
                ulonglong2 hb =
                    *reinterpret_cast<const ulonglong2*>(&S.h1[b * Hh + k4 * 4]);
                #pragma unroll
                for (int c = 0; c < 4; ++c) {
                    acc[c][b] = f32x2_fma(ha.x, wa[c].x, acc[c][b]);
                    acc[c][b] = f32x2_fma(ha.y, wa[c].y, acc[c][b]);
                    acc[c][b] = f32x2_fma(hb.x, wb[c].x, acc[c][b]);
                    acc[c][b] = f32x2_fma(hb.y, wb[c].y, acc[c][b]);
                }
            }
        }
        #pragma unroll
        for (int c = 0; c < 4; ++c)
            #pragma unroll
            for (int b = 0; b < MB; ++b) {
                F2U u; u.u = acc[c][b];
                S.part[kg][c][b][jj] = u.f.x + u.f.y;
            }
        __syncthreads();

        // ========= layer 1 reduce + tanh =====================================
        #pragma unroll
        for (int b = 0; b < MB; ++b) {
            float s = (S.part[0][kg][b][jj] + S.part[1][kg][b][jj])
                    + (S.part[2][kg][b][jj] + S.part[3][kg][b][jj]);
            S.h1[b * Hh + colr] = tanhf(bias1r + s);
        }
        __syncthreads();
    }

    // ---------------- final FC: out[b] = h1_last @ W_fc^T + b_fc -------------
    if (t < Cc * MB) {
        int c = t / MB, b = t % MB;
        float s = b_fc[c];
        #pragma unroll 8
        for (int h = 0; h < Hh; ++h) s += S.h1[b * Hh + h] * W_fc[c * Hh + h];
        out[(b0 + b) * Cc + c] = s;
    }
}

extern "C" void kernel_launch(void* const* d_in, const int* in_sizes, int n_in,
                              void* d_out, int out_size) {
    const float* x     = (const float*)d_in[0];
    const float* W_ih0 = (const float*)d_in[1];
    const float* W_hh0 = (const float*)d_in[2];
    const float* b_ih0 = (const float*)d_in[3];
    const float* b_hh0 = (const float*)d_in[4];
    const float* W_ih1 = (const float*)d_in[5];
    const float* W_hh1 = (const float*)d_in[6];
    const float* b_ih1 = (const float*)d_in[7];
    const float* b_hh1 = (const float*)d_in[8];
    const float* W_fc  = (const float*)d_in[9];
    const float* b_fc  = (const float*)d_in[10];
    float* out = (float*)d_out;

    cudaFuncSetAttribute(rnn_fused_kernel,
                         cudaFuncAttributeMaxDynamicSharedMemorySize,
                         (int)sizeof(Smem));
    pack_kernel<<<Hh, Hh>>>(W_hh0, W_ih1, W_hh1);
    rnn_fused_kernel<<<NCTA, THR, sizeof(Smem)>>>(
        x, W_ih0, b_ih0, b_hh0, b_ih1, b_hh1, W_fc, b_fc, out);
}

// round 7
// speedup vs baseline: 1.6065x; 1.0006x over previous
#include <cuda_runtime.h>

#define Hh 256
#define Tt 187
#define Bb 1024
#define Cc 5
#define MB 4
#define NCTA (Bb / MB)   // 256 CTAs -> 2 per SM
#define THR 256          // 8 warps = 4 k-groups x 2 jj-halves

// Packed weights: layout [k/4][j][4] so a thread loads float4 of 4 consecutive
// k's for column j, coalesced across lanes (16B/lane, lanes = consecutive j).
__device__ float g_Wp0[Hh * Hh];      // packed W_hh0
__device__ float g_Wpih1[Hh * Hh];    // packed W_ih1
__device__ float g_Wp1[Hh * Hh];      // packed W_hh1

__global__ void pack_kernel(const float* __restrict__ W_hh0,
                            const float* __restrict__ W_ih1,
                            const float* __restrict__ W_hh1) {
    int j = blockIdx.x;
    int k = threadIdx.x;
    int src = j * Hh + k;
    int dst = ((k >> 2) * Hh + j) * 4 + (k & 3);
    g_Wp0[dst]   = W_hh0[src];
    g_Wpih1[dst] = W_ih1[src];
    g_Wp1[dst]   = W_hh1[src];
}

union F2U { unsigned long long u; float2 f; };

__device__ __forceinline__ unsigned long long f32x2_fma(
    unsigned long long a, unsigned long long b, unsigned long long c) {
    unsigned long long d;
    asm("fma.rn.f32x2 %0, %1, %2, %3;" : "=l"(d) : "l"(a), "l"(b), "l"(c));
    return d;
}

struct Smem {
    float h0[MB * Hh];              // 4 KB
    float h1[MB * Hh];              // 4 KB
    float part[4][4][MB][64];       // [kg][c][b][jj] 16 KB
    float xs[MB * Tt];              // ~3 KB
    float wih0s[Hh];
    float bias0s[Hh];
    float bias1s[Hh];
};

__global__ void __launch_bounds__(THR, 2) rnn_fused_kernel(
    const float* __restrict__ x,
    const float* __restrict__ W_ih0,
    const float* __restrict__ b_ih0, const float* __restrict__ b_hh0,
    const float* __restrict__ b_ih1, const float* __restrict__ b_hh1,
    const float* __restrict__ W_fc,  const float* __restrict__ b_fc,
    float* __restrict__ out)
{
    extern __shared__ __align__(16) char smem_raw[];
    Smem& S = *reinterpret_cast<Smem*>(smem_raw);

    const int t    = threadIdx.x;
    const int lane = t & 31;
    const int w    = t >> 5;
    const int kg   = w >> 1;           // k-group 0..3, 16 k4-iters each
    const int half = w & 1;            // jj-half
    const int jj   = half * 32 + lane; // 0..63
    const int b0   = blockIdx.x * MB;

    for (int i = t; i < MB * Tt; i += THR) S.xs[i] = x[b0 * Tt + i];
    for (int i = t; i < MB * Hh; i += THR) { S.h0[i] = 0.f; S.h1[i] = 0.f; }
    for (int i = t; i < Hh; i += THR) {
        S.wih0s[i]  = W_ih0[i];
        S.bias0s[i] = b_ih0[i] + b_hh0[i];
        S.bias1s[i] = b_ih1[i] + b_hh1[i];
    }
    __syncthreads();

    // This thread's reducer role: column colr = jj + 64*kg (warp w == task w)
    const int   colr   = jj + 64 * kg;
    const float wih0r  = S.wih0s[colr];
    const float bias0r = S.bias0s[colr];
    const float bias1r = S.bias1s[colr];

    const int k4lo = kg * 16;

    for (int step = 0; step < Tt; ++step) {
        // ========= layer 0 partials: acc[c][b] over k-slice kg ===============
        unsigned long long acc[4][MB];
        #pragma unroll
        for (int c = 0; c < 4; ++c)
            #pragma unroll
            for (int b = 0; b < MB; ++b) acc[c][b] = 0ULL;

        #pragma unroll 4
        for (int kk = 0; kk < 16; ++kk) {
            const int k4 = k4lo + kk;
            ulonglong2 wv[4];
            #pragma unroll
            for (int c = 0; c < 4; ++c)
                wv[c] = *reinterpret_cast<const ulonglong2*>(
                    &g_Wp0[(k4 * Hh + jj + 64 * c) * 4]);
            #pragma unroll
            for (int b = 0; b < MB; ++b) {
                ulonglong2 h =
                    *reinterpret_cast<const ulonglong2*>(&S.h0[b * Hh + k4 * 4]);
                #pragma unroll
                for (int c = 0; c < 4; ++c) {
                    acc[c][b] = f32x2_fma(h.x, wv[c].x, acc[c][b]);
                    acc[c][b] = f32x2_fma(h.y, wv[c].y, acc[c][b]);
                }
            }
        }
        #pragma unroll
        for (int c = 0; c < 4; ++c)
            #pragma unroll
            for (int b = 0; b < MB; ++b) {
                F2U u; u.u = acc[c][b];
                S.part[kg][c][b][jj] = u.f.x + u.f.y;
            }
        __syncthreads();

        // ========= layer 0 reduce + tanh (balanced: all 8 warps) =============
        #pragma unroll
        for (int b = 0; b < MB; ++b) {
            float s = (S.part[0][kg][b][jj] + S.part[1][kg][b][jj])
                    + (S.part[2][kg][b][jj] + S.part[3][kg][b][jj]);
            float pre = S.xs[b * Tt + step] * wih0r + bias0r + s;
            S.h0[b * Hh + colr] = tanhf(pre);
        }
        __syncthreads();

        // ========= layer 1 partials ==========================================
        #pragma unroll
        for (int c = 0; c < 4; ++c)
            #pragma unroll
            for (int b = 0; b < MB; ++b) acc[c][b] = 0ULL;

        #pragma unroll 4
        for (int kk = 0; kk < 16; ++kk) {
            const int k4 = k4lo + kk;
            ulonglong2 wa[4], wb[4];
            #pragma unroll
            for (int c = 0; c < 4; ++c) {
                wa[c] = *reinterpret_cast<const ulonglong2*>(
                    &g_Wpih1[(k4 * Hh + jj + 64 * c) * 4]);
                wb[c] = *reinterpret_cast<const ulonglong2*>(
                    &g_Wp1[(k4 * Hh + jj + 64 * c) * 4]);
            }
            #pragma unroll
            for (int b = 0; b < MB; ++b) {
                ulonglong2 ha =
                    *reinterpret_cast<const ulonglong2*>(&S.h0[b * Hh + k4 * 4]);
                ulonglong2 hb =
                    *reinterpret_cast<const ulonglong2*>(&S.h1[b * Hh + k4 * 4]);
                #pragma unroll
                for (int c = 0; c < 4; ++c) {
                    acc[c][b] = f32x2_fma(ha.x, wa[c].x, acc[c][b]);
                    acc[c][b] = f32x2_fma(ha.y, wa[c].y, acc[c][b]);
                    acc[c][b] = f32x2_fma(hb.x, wb[c].x, acc[c][b]);
                    acc[c][b] = f32x2_fma(hb.y, wb[c].y, acc[c][b]);
                }
            }
        }
        #pragma unroll
        for (int c = 0; c < 4; ++c)
            #pragma unroll
            for (int b = 0; b < MB; ++b) {
                F2U u; u.u = acc[c][b];
                S.part[kg][c][b][jj] = u.f.x + u.f.y;
            }
        __syncthreads();

        // ========= layer 1 reduce + tanh =====================================
        #pragma unroll
        for (int b = 0; b < MB; ++b) {
            float s = (S.part[0][kg][b][jj] + S.part[1][kg][b][jj])
                    + (S.part[2][kg][b][jj] + S.part[3][kg][b][jj]);
            S.h1[b * Hh + colr] = tanhf(bias1r + s);
        }
        __syncthreads();
    }

    // ---------------- final FC: out[b] = h1_last @ W_fc^T + b_fc -------------
    if (t < Cc * MB) {
        int c = t / MB, b = t % MB;
        float s = b_fc[c];
        #pragma unroll 8
        for (int h = 0; h < Hh; ++h) s += S.h1[b * Hh + h] * W_fc[c * Hh + h];
        out[(b0 + b) * Cc + c] = s;
    }
}

extern "C" void kernel_launch(void* const* d_in, const int* in_sizes, int n_in,
                              void* d_out, int out_size) {
    const float* x     = (const float*)d_in[0];
    const float* W_ih0 = (const float*)d_in[1];
    const float* W_hh0 = (const float*)d_in[2];
    const float* b_ih0 = (const float*)d_in[3];
    const float* b_hh0 = (const float*)d_in[4];
    const float* W_ih1 = (const float*)d_in[5];
    const float* W_hh1 = (const float*)d_in[6];
    const float* b_ih1 = (const float*)d_in[7];
    const float* b_hh1 = (const float*)d_in[8];
    const float* W_fc  = (const float*)d_in[9];
    const float* b_fc  = (const float*)d_in[10];
    float* out = (float*)d_out;

    cudaFuncSetAttribute(rnn_fused_kernel,
                         cudaFuncAttributeMaxDynamicSharedMemorySize,
                         (int)sizeof(Smem));
    pack_kernel<<<Hh, Hh>>>(W_hh0, W_ih1, W_hh1);
    rnn_fused_kernel<<<NCTA, THR, sizeof(Smem)>>>(
        x, W_ih0, b_ih0, b_hh0, b_ih1, b_hh1, W_fc, b_fc, out);
}